// round 12
// baseline (speedup 1.0000x reference)
#include <cuda_runtime.h>

// Banded attention |i-j|<=4: B=256, S=128, D=1024, H=16, HD=64, fp32.
// Grid 8192: one CTA (128 thr) per (b,h,half) -> 64 queries. K window (72
// clamped rows) staged via cp.async into smem (stride 68 floats).
// TWO PHASES split by a barrier, weights passed via smem:
//   Score phase: thread = (query, half-window); computes 5 full 64-dim dots
//     solo (Q-LDG chunk reused over 5 K-LDS rows, 10 indep FMA chains).
//     NO shuffles; 1 shfl per query for the denominator. exp outside chains.
//   V phase: R9-proven pair-sharing loop, weights/inv via smem broadcast,
//     V from global (L2/L1-resident), packed f32x2 FMA, .128 everywhere.

constexpr int S_LEN   = 128;
constexpr int D_MODEL = 1024;
constexpr int THREADS = 128;
constexpr int QB      = 64;        // queries per CTA
constexpr int KROWS   = QB + 8;    // 72 staged rows (clamped)
constexpr int KSTR    = 68;        // K smem row stride (floats), 16B-aligned
constexpr int WSTR    = 12;        // weight row stride (floats)
constexpr int WROWS   = 10;

using u64 = unsigned long long;

__device__ __forceinline__ u64 f2_fma(u64 a, u64 b, u64 c) {
    u64 d; asm("fma.rn.f32x2 %0,%1,%2,%3;" : "=l"(d) : "l"(a), "l"(b), "l"(c)); return d;
}
__device__ __forceinline__ u64 f2_mul(u64 a, u64 b) {
    u64 d; asm("mul.rn.f32x2 %0,%1,%2;" : "=l"(d) : "l"(a), "l"(b)); return d;
}
__device__ __forceinline__ u64 f2_pack(float lo, float hi) {
    u64 d; asm("mov.b64 %0,{%1,%2};" : "=l"(d) : "f"(lo), "f"(hi)); return d;
}
__device__ __forceinline__ float2 f2_unpack(u64 a) {
    float lo, hi; asm("mov.b64 {%0,%1},%2;" : "=f"(lo), "=f"(hi) : "l"(a));
    return make_float2(lo, hi);
}
__device__ __forceinline__ void ld4(const float* __restrict__ p, u64& a, u64& b) {
    float4 f = *reinterpret_cast<const float4*>(p);
    a = f2_pack(f.x, f.y);
    b = f2_pack(f.z, f.w);
}
__device__ __forceinline__ void st4(float* __restrict__ p, u64 a, u64 b) {
    float2 lo = f2_unpack(a), hi = f2_unpack(b);
    *reinterpret_cast<float4*>(p) = make_float4(lo.x, lo.y, hi.x, hi.y);
}
__device__ __forceinline__ void cp_async16(unsigned s, const void* g) {
    asm volatile("cp.async.ca.shared.global [%0], [%1], 16;" :: "r"(s), "l"(g));
}

__global__ __launch_bounds__(THREADS, 8)
void band_attn_kernel(const float* __restrict__ q,
                      const float* __restrict__ k,
                      const float* __restrict__ v,
                      float* __restrict__ out)
{
    extern __shared__ float smem[];
    float* ks  = smem;                       // [72][68]
    float* wsm = smem + KROWS * KSTR;        // [64][12] weights
    float* dsm = wsm + QB * WSTR;            // [64] 1/den

    const int tid   = threadIdx.x;
    const int cta   = blockIdx.x;            // 0..8191
    const int bh    = cta >> 1;
    const int half  = cta & 1;
    const int qbase = half * QB;
    const int b     = bh >> 4;
    const int h     = bh & 15;
    const size_t base = (size_t)b * S_LEN * D_MODEL + (size_t)h * 64;

    const float* kb = k   + base;
    const float* vb = v   + base;
    const float* qb = q   + base;
    float*       ob = out + base;

    // Stage K window: smem row r holds K[clamp(qbase-4+r)]; 1152 x 16B chunks.
    const unsigned ks_s = (unsigned)__cvta_generic_to_shared(ks);
    #pragma unroll
    for (int it = 0; it < 9; ++it) {
        int idx = it * THREADS + tid;        // 0..1151
        int row = idx >> 4;
        int c4  = idx & 15;
        int gr  = min(max(qbase - 4 + row, 0), S_LEN - 1);
        cp_async16(ks_s + (unsigned)(row * KSTR + c4 * 4) * 4u,
                   kb + (size_t)gr * D_MODEL + c4 * 4);
    }
    asm volatile("cp.async.commit_group;");
    asm volatile("cp.async.wait_group 0;");
    __syncthreads();

    // ================= Score phase =================
    // thread -> (query ql, half-window hh): rows r = 5*hh + j, j=0..4.
    {
        const int ql = tid >> 1;             // 0..63
        const int hh = tid & 1;
        const int i  = qbase + ql;
        const float* qrow = qb + (size_t)i * D_MODEL;
        const float* kloc = ks + (ql + 5 * hh) * KSTR;

        u64 accA[5] = {0, 0, 0, 0, 0};
        u64 accB[5] = {0, 0, 0, 0, 0};
        #pragma unroll
        for (int c = 0; c < 16; ++c) {
            u64 qa, qc;
            ld4(qrow + c * 4, qa, qc);       // LDG.128, reused over 5 rows
            #pragma unroll
            for (int j = 0; j < 5; ++j) {
                u64 ka, kc;
                ld4(kloc + j * KSTR + c * 4, ka, kc);   // LDS.128
                accA[j] = f2_fma(qa, ka, accA[j]);
                accB[j] = f2_fma(qc, kc, accB[j]);
            }
        }

        float wsum = 0.f;
        #pragma unroll
        for (int j = 0; j < 5; ++j) {
            float2 a = f2_unpack(accA[j]);
            float2 c = f2_unpack(accB[j]);
            float s = (a.x + a.y + c.x + c.y) * 0.125f;
            const int r    = 5 * hh + j;
            const int jabs = i - 4 + r;
            const bool ok  = (r <= 8) && (jabs >= 0) && (jabs < S_LEN);
            const float w  = ok ? __expf(s) : 0.f;
            wsm[ql * WSTR + r] = w;
            wsum += w;
        }
        wsum += __shfl_xor_sync(0xffffffffu, wsum, 1);   // pair shares query
        if (hh == 0) dsm[ql] = 1.0f / wsum;
    }
    __syncthreads();

    // ================= V phase (R9 structure, weights from smem) =========
    const int warp = tid >> 5;
    const int lane = tid & 31;
    const int g    = lane >> 3;              // subgroup 0..3
    const int l    = lane & 7;
    const int c0   = 4 * l;

    #pragma unroll 1
    for (int t = 0; t < 2; ++t) {
        const int il = warp * 16 + t * 8 + g * 2;   // CTA-local even query
        const int i0 = qbase + il;
        const int i1 = i0 + 1;

        const float inv0 = dsm[il];
        const float inv1 = dsm[il + 1];
        const float* w0p = wsm + il * WSTR;
        const float* w1p = wsm + (il + 1) * WSTR;

        u64 acc0[4] = {0, 0, 0, 0};
        u64 acc1[4] = {0, 0, 0, 0};

        #pragma unroll
        for (int r = 0; r < WROWS; ++r) {
            const float w0 = w0p[r];                      // LDS broadcast
            const float w1 = (r >= 1) ? w1p[r - 1] : 0.f; // i1's window shift
            const int jc = min(max(i0 - 4 + r, 0), S_LEN - 1);

            u64 vv[4];
            const float* vrow = vb + (size_t)jc * D_MODEL + c0;
            ld4(vrow,      vv[0], vv[1]);                 // LDG.128 x2
            ld4(vrow + 32, vv[2], vv[3]);

            const u64 e0p = f2_pack(w0, w0);
            const u64 e1p = f2_pack(w1, w1);
            #pragma unroll
            for (int kk = 0; kk < 4; ++kk) {
                acc0[kk] = f2_fma(e0p, vv[kk], acc0[kk]);
                acc1[kk] = f2_fma(e1p, vv[kk], acc1[kk]);
            }
        }

        const u64 i0p = f2_pack(inv0, inv0);
        const u64 i1p = f2_pack(inv1, inv1);
        float* o0 = ob + (size_t)i0 * D_MODEL + c0;
        float* o1 = ob + (size_t)i1 * D_MODEL + c0;
        st4(o0,      f2_mul(acc0[0], i0p), f2_mul(acc0[1], i0p));
        st4(o0 + 32, f2_mul(acc0[2], i0p), f2_mul(acc0[3], i0p));
        st4(o1,      f2_mul(acc1[0], i1p), f2_mul(acc1[1], i1p));
        st4(o1 + 32, f2_mul(acc1[2], i1p), f2_mul(acc1[3], i1p));
    }
}

extern "C" void kernel_launch(void* const* d_in, const int* in_sizes, int n_in,
                              void* d_out, int out_size)
{
    const float* q = (const float*)d_in[0];
    const float* k = (const float*)d_in[1];
    const float* v = (const float*)d_in[2];
    float* out = (float*)d_out;

    const int smem_floats = KROWS * KSTR + QB * WSTR + QB;
    const int smem_bytes  = smem_floats * (int)sizeof(float);  // ~23KB
    cudaFuncSetAttribute(band_attn_kernel,
                         cudaFuncAttributeMaxDynamicSharedMemorySize, smem_bytes);

    const int n_cta = 256 * 16 * 2;  // B * H * 2 halves
    band_attn_kernel<<<n_cta, THREADS, smem_bytes>>>(q, k, v, out);
}

// round 13
// speedup vs baseline: 1.1553x; 1.1553x over previous
#include <cuda_runtime.h>

// Banded attention |i-j|<=4: B=256, S=128, D=1024, H=16, HD=64, fp32.
// Grid 8192: one CTA (128 thr) per (b,h,half) -> 64 queries.
// Three phases, ONE 18.4KB tile buffer reused for K then V (K dead after
// scores), so 8 CTAs/SM is preserved:
//   1) cp.async.cg K window (72 clamped rows) -> score pass (R9's proven
//      8-lane-subgroup pair-sharing, quarter-warp LDS.128, 3-step shuffle,
//      online exp); weights -> smem (lane-0 STS), 1/den -> smem.
//   2) barrier; cp.async.cg V window into the SAME buffer; barrier.
//   3) V pass: weights/inv via smem broadcast, V rows via LDS.128,
//      branchless (invalid weight slots pre-zeroed), packed f32x2 FMA.

constexpr int S_LEN   = 128;
constexpr int D_MODEL = 1024;
constexpr int THREADS = 128;
constexpr int QB      = 64;        // queries per CTA
constexpr int KROWS   = QB + 8;    // 72 staged rows (clamped)
constexpr int WSTR    = 12;        // weight row stride (floats)
constexpr int WROWS   = 10;

using u64 = unsigned long long;

__device__ __forceinline__ u64 f2_fma(u64 a, u64 b, u64 c) {
    u64 d; asm("fma.rn.f32x2 %0,%1,%2,%3;" : "=l"(d) : "l"(a), "l"(b), "l"(c)); return d;
}
__device__ __forceinline__ u64 f2_mul(u64 a, u64 b) {
    u64 d; asm("mul.rn.f32x2 %0,%1,%2;" : "=l"(d) : "l"(a), "l"(b)); return d;
}
__device__ __forceinline__ u64 f2_pack(float lo, float hi) {
    u64 d; asm("mov.b64 %0,{%1,%2};" : "=l"(d) : "f"(lo), "f"(hi)); return d;
}
__device__ __forceinline__ float2 f2_unpack(u64 a) {
    float lo, hi; asm("mov.b64 {%0,%1},%2;" : "=f"(lo), "=f"(hi) : "l"(a));
    return make_float2(lo, hi);
}
__device__ __forceinline__ void ld4(const float* __restrict__ p, u64& a, u64& b) {
    float4 f = *reinterpret_cast<const float4*>(p);
    a = f2_pack(f.x, f.y);
    b = f2_pack(f.z, f.w);
}
__device__ __forceinline__ void st4(float* __restrict__ p, u64 a, u64 b) {
    float2 lo = f2_unpack(a), hi = f2_unpack(b);
    *reinterpret_cast<float4*>(p) = make_float4(lo.x, lo.y, hi.x, hi.y);
}
__device__ __forceinline__ void cp_async16_cg(unsigned s, const void* g) {
    asm volatile("cp.async.cg.shared.global [%0], [%1], 16;" :: "r"(s), "l"(g));
}

__global__ __launch_bounds__(THREADS, 8)
void band_attn_kernel(const float* __restrict__ q,
                      const float* __restrict__ k,
                      const float* __restrict__ v,
                      float* __restrict__ out)
{
    extern __shared__ float smem[];
    float* tile = smem;                      // [72][64]: K then V
    float* wsm  = smem + KROWS * 64;         // [64][12] weights (i0-frame idx)
    float* dsm  = wsm + QB * WSTR;           // [64] 1/den

    const int tid   = threadIdx.x;
    const int cta   = blockIdx.x;            // 0..8191
    const int bh    = cta >> 1;
    const int half  = cta & 1;
    const int qbase = half * QB;
    const int b     = bh >> 4;
    const int h     = bh & 15;
    const size_t base = (size_t)b * S_LEN * D_MODEL + (size_t)h * 64;

    const float* kb = k   + base;
    const float* vb = v   + base;
    const float* qb = q   + base;
    float*       ob = out + base;

    const unsigned tile_s = (unsigned)__cvta_generic_to_shared(tile);

    // ---- Stage K window: smem row r holds K[clamp(qbase-4+r)] ----
    #pragma unroll
    for (int it = 0; it < 9; ++it) {
        int idx = it * THREADS + tid;        // 0..1151
        int row = idx >> 4;
        int c4  = idx & 15;
        int gr  = min(max(qbase - 4 + row, 0), S_LEN - 1);
        cp_async16_cg(tile_s + (unsigned)(row * 64 + c4 * 4) * 4u,
                      kb + (size_t)gr * D_MODEL + c4 * 4);
    }
    asm volatile("cp.async.commit_group;");

    // Zero weight+den region (832 floats) while K stage flies.
    #pragma unroll
    for (int i = tid; i < QB * WSTR + QB; i += THREADS) wsm[i] = 0.f;

    const int warp = tid >> 5;               // 0..3
    const int lane = tid & 31;
    const int g    = lane >> 3;              // subgroup 0..3
    const int l    = lane & 7;
    const int c0   = 4 * l;
    const u64 scale2 = f2_pack(0.125f, 0.125f);

    // Hoist t=0 Q loads (overlap K stage).
    u64 q0[4], q1[4];
    {
        const int i0 = qbase + warp * 16 + g * 2;
        const float* q0p = qb + (size_t)i0 * D_MODEL + c0;
        const float* q1p = qb + (size_t)(i0 + 1) * D_MODEL + c0;
        ld4(q0p,      q0[0], q0[1]);
        ld4(q0p + 32, q0[2], q0[3]);
        ld4(q1p,      q1[0], q1[1]);
        ld4(q1p + 32, q1[2], q1[3]);
        #pragma unroll
        for (int kk = 0; kk < 4; ++kk) {
            q0[kk] = f2_mul(q0[kk], scale2);
            q1[kk] = f2_mul(q1[kk], scale2);
        }
    }

    asm volatile("cp.async.wait_group 0;");
    __syncthreads();

    // ================= Score pass (weights -> smem) =================
    #pragma unroll 1
    for (int t = 0; t < 2; ++t) {
        const int il = warp * 16 + t * 8 + g * 2;   // CTA-local even query
        const int i0 = qbase + il;

        if (t == 1) {
            const float* q0p = qb + (size_t)i0 * D_MODEL + c0;
            const float* q1p = qb + (size_t)(i0 + 1) * D_MODEL + c0;
            ld4(q0p,      q0[0], q0[1]);
            ld4(q0p + 32, q0[2], q0[3]);
            ld4(q1p,      q1[0], q1[1]);
            ld4(q1p + 32, q1[2], q1[3]);
            #pragma unroll
            for (int kk = 0; kk < 4; ++kk) {
                q0[kk] = f2_mul(q0[kk], scale2);
                q1[kk] = f2_mul(q1[kk], scale2);
            }
        }

        float den0 = 0.f, den1 = 0.f;
        #pragma unroll
        for (int r = 0; r < WROWS; ++r) {
            const int j = i0 - 4 + r;

            u64 kv[4];
            const float* krow = tile + (il + r) * 64 + c0;   // LDS.128 x2
            ld4(krow,      kv[0], kv[1]);
            ld4(krow + 32, kv[2], kv[3]);

            u64 a0 = f2_mul(q0[0], kv[0]);
            a0 = f2_fma(q0[1], kv[1], a0);
            a0 = f2_fma(q0[2], kv[2], a0);
            a0 = f2_fma(q0[3], kv[3], a0);
            u64 a1 = f2_mul(q1[0], kv[0]);
            a1 = f2_fma(q1[1], kv[1], a1);
            a1 = f2_fma(q1[2], kv[2], a1);
            a1 = f2_fma(q1[3], kv[3], a1);

            float2 s0 = f2_unpack(a0);
            float2 s1 = f2_unpack(a1);
            float p0 = s0.x + s0.y;
            float p1 = s1.x + s1.y;

            p0 += __shfl_xor_sync(0xffffffffu, p0, 1);
            p0 += __shfl_xor_sync(0xffffffffu, p0, 2);
            p0 += __shfl_xor_sync(0xffffffffu, p0, 4);
            p1 += __shfl_xor_sync(0xffffffffu, p1, 1);
            p1 += __shfl_xor_sync(0xffffffffu, p1, 2);
            p1 += __shfl_xor_sync(0xffffffffu, p1, 4);

            const bool in_seq = (j >= 0) && (j < S_LEN);
            const float e0 = (in_seq && r <= 8) ? __expf(p0) : 0.f;
            const float e1 = (in_seq && r >= 1) ? __expf(p1) : 0.f;
            den0 += e0;
            den1 += e1;

            if (l == 0) {                    // uniform across subgroup
                if (r <= 8) wsm[il * WSTR + r] = e0;
                if (r >= 1) wsm[(il + 1) * WSTR + r] = e1;
            }
        }
        if (l == 0) {
            dsm[il]     = 1.0f / den0;
            dsm[il + 1] = 1.0f / den1;
        }
    }

    // ================= Swap buffer: K -> V =================
    __syncthreads();                          // all K reads + weight writes done
    #pragma unroll
    for (int it = 0; it < 9; ++it) {
        int idx = it * THREADS + tid;
        int row = idx >> 4;
        int c4  = idx & 15;
        int gr  = min(max(qbase - 4 + row, 0), S_LEN - 1);
        cp_async16_cg(tile_s + (unsigned)(row * 64 + c4 * 4) * 4u,
                      vb + (size_t)gr * D_MODEL + c4 * 4);
    }
    asm volatile("cp.async.commit_group;");
    asm volatile("cp.async.wait_group 0;");
    __syncthreads();

    // ================= V pass (branchless, all smem) =================
    #pragma unroll 1
    for (int t = 0; t < 2; ++t) {
        const int il = warp * 16 + t * 8 + g * 2;
        const int i0 = qbase + il;

        const float inv0 = dsm[il];
        const float inv1 = dsm[il + 1];
        const float* w0p = wsm + il * WSTR;        // slots 9 / 0 are zero
        const float* w1p = wsm + (il + 1) * WSTR;

        u64 acc0[4] = {0, 0, 0, 0};
        u64 acc1[4] = {0, 0, 0, 0};

        #pragma unroll
        for (int r = 0; r < WROWS; ++r) {
            const float w0 = w0p[r];               // LDS broadcast
            const float w1 = w1p[r];

            u64 vv[4];
            const float* vrow = tile + (il + r) * 64 + c0;   // LDS.128 x2
            ld4(vrow,      vv[0], vv[1]);
            ld4(vrow + 32, vv[2], vv[3]);

            const u64 e0p = f2_pack(w0, w0);
            const u64 e1p = f2_pack(w1, w1);
            #pragma unroll
            for (int kk = 0; kk < 4; ++kk) {
                acc0[kk] = f2_fma(e0p, vv[kk], acc0[kk]);
                acc1[kk] = f2_fma(e1p, vv[kk], acc1[kk]);
            }
        }

        const u64 i0p = f2_pack(inv0, inv0);
        const u64 i1p = f2_pack(inv1, inv1);
        float* o0 = ob + (size_t)i0 * D_MODEL + c0;
        float* o1 = ob + (size_t)(i0 + 1) * D_MODEL + c0;
        st4(o0,      f2_mul(acc0[0], i0p), f2_mul(acc0[1], i0p));
        st4(o0 + 32, f2_mul(acc0[2], i0p), f2_mul(acc0[3], i0p));
        st4(o1,      f2_mul(acc1[0], i1p), f2_mul(acc1[1], i1p));
        st4(o1 + 32, f2_mul(acc1[2], i1p), f2_mul(acc1[3], i1p));
    }
}

extern "C" void kernel_launch(void* const* d_in, const int* in_sizes, int n_in,
                              void* d_out, int out_size)
{
    const float* q = (const float*)d_in[0];
    const float* k = (const float*)d_in[1];
    const float* v = (const float*)d_in[2];
    float* out = (float*)d_out;

    const int smem_floats = KROWS * 64 + QB * WSTR + QB;   // 5440
    const int smem_bytes  = smem_floats * (int)sizeof(float);  // 21760
    cudaFuncSetAttribute(band_attn_kernel,
                         cudaFuncAttributeMaxDynamicSharedMemorySize, smem_bytes);

    const int n_cta = 256 * 16 * 2;  // B * H * 2 halves
    band_attn_kernel<<<n_cta, THREADS, smem_bytes>>>(q, k, v, out);
}

// round 14
// speedup vs baseline: 1.2155x; 1.0521x over previous
#include <cuda_runtime.h>

// Banded attention |i-j|<=4: B=256, S=128, D=1024, H=16, HD=64, fp32.
// Grid 16384: one CTA (128 thr) per (b,h,quarter) -> 32 queries. K window
// (40 clamped rows, 10KB) staged via cp.async.cg (L1-bypass); V from global
// (L1/L2-resident). NO t-loop: 16 pairs = 4 warps x 4 subgroups cover all
// 32 queries in one pass. R9's proven inner loop: 8-lane subgroups, adjacent
// query pairs over a shared 10-row window, quarter-warp .128 accesses,
// 3-step shuffle reduction, online softmax, packed f32x2 FMA. 9 CTAs/SM.

constexpr int S_LEN   = 128;
constexpr int D_MODEL = 1024;
constexpr int THREADS = 128;
constexpr int QB      = 32;        // queries per CTA
constexpr int KROWS   = QB + 8;    // 40 staged rows (clamped)
constexpr int WROWS   = 10;

using u64 = unsigned long long;

__device__ __forceinline__ u64 f2_fma(u64 a, u64 b, u64 c) {
    u64 d; asm("fma.rn.f32x2 %0,%1,%2,%3;" : "=l"(d) : "l"(a), "l"(b), "l"(c)); return d;
}
__device__ __forceinline__ u64 f2_mul(u64 a, u64 b) {
    u64 d; asm("mul.rn.f32x2 %0,%1,%2;" : "=l"(d) : "l"(a), "l"(b)); return d;
}
__device__ __forceinline__ u64 f2_pack(float lo, float hi) {
    u64 d; asm("mov.b64 %0,{%1,%2};" : "=l"(d) : "f"(lo), "f"(hi)); return d;
}
__device__ __forceinline__ float2 f2_unpack(u64 a) {
    float lo, hi; asm("mov.b64 {%0,%1},%2;" : "=f"(lo), "=f"(hi) : "l"(a));
    return make_float2(lo, hi);
}
__device__ __forceinline__ void ld4(const float* __restrict__ p, u64& a, u64& b) {
    float4 f = *reinterpret_cast<const float4*>(p);
    a = f2_pack(f.x, f.y);
    b = f2_pack(f.z, f.w);
}
__device__ __forceinline__ void st4(float* __restrict__ p, u64 a, u64 b) {
    float2 lo = f2_unpack(a), hi = f2_unpack(b);
    *reinterpret_cast<float4*>(p) = make_float4(lo.x, lo.y, hi.x, hi.y);
}
__device__ __forceinline__ void cp_async16_cg(unsigned s, const void* g) {
    asm volatile("cp.async.cg.shared.global [%0], [%1], 16;" :: "r"(s), "l"(g));
}

__global__ __launch_bounds__(THREADS, 9)
void band_attn_kernel(const float* __restrict__ q,
                      const float* __restrict__ k,
                      const float* __restrict__ v,
                      float* __restrict__ out)
{
    extern __shared__ float smem[];   // K window [40][64]
    float* ks = smem;

    const int tid   = threadIdx.x;
    const int cta   = blockIdx.x;     // 0..16383
    const int bh    = cta >> 2;
    const int quart = cta & 3;
    const int qbase = quart * QB;
    const int b     = bh >> 4;
    const int h     = bh & 15;
    const size_t base = (size_t)b * S_LEN * D_MODEL + (size_t)h * 64;

    const float* kb = k   + base;
    const float* vb = v   + base;
    const float* qb = q   + base;
    float*       ob = out + base;

    // Stage K window: smem row r holds K[clamp(qbase-4+r)]; 640 x 16B chunks.
    const unsigned ks_s = (unsigned)__cvta_generic_to_shared(ks);
    #pragma unroll
    for (int it = 0; it < 5; ++it) {
        int idx = it * THREADS + tid;       // 0..639
        int row = idx >> 4;
        int c4  = idx & 15;
        int gr  = min(max(qbase - 4 + row, 0), S_LEN - 1);
        cp_async16_cg(ks_s + (unsigned)(row * 64 + c4 * 4) * 4u,
                      kb + (size_t)gr * D_MODEL + c4 * 4);
    }
    asm volatile("cp.async.commit_group;");

    const int warp = tid >> 5;              // 0..3
    const int lane = tid & 31;
    const int g    = lane >> 3;             // subgroup 0..3
    const int l    = lane & 7;
    const int c0   = 4 * l;
    const u64 scale2 = f2_pack(0.125f, 0.125f);

    const int il = warp * 8 + g * 2;        // CTA-local even query (0..30)
    const int i0 = qbase + il;
    const int i1 = i0 + 1;

    // Q loads overlap the in-flight K stage.
    u64 q0[4], q1[4];
    {
        const float* q0p = qb + (size_t)i0 * D_MODEL + c0;
        const float* q1p = qb + (size_t)i1 * D_MODEL + c0;
        ld4(q0p,      q0[0], q0[1]);
        ld4(q0p + 32, q0[2], q0[3]);
        ld4(q1p,      q1[0], q1[1]);
        ld4(q1p + 32, q1[2], q1[3]);
        #pragma unroll
        for (int kk = 0; kk < 4; ++kk) {
            q0[kk] = f2_mul(q0[kk], scale2);
            q1[kk] = f2_mul(q1[kk], scale2);
        }
    }

    asm volatile("cp.async.wait_group 0;");
    __syncthreads();

    float den0 = 0.f, den1 = 0.f;
    u64 acc0[4] = {0, 0, 0, 0};
    u64 acc1[4] = {0, 0, 0, 0};

    #pragma unroll
    for (int r = 0; r < WROWS; ++r) {
        const int j = i0 - 4 + r;

        u64 kv[4];
        {
            const float* krow = ks + (il + r) * 64 + c0;   // LDS.128 x2
            ld4(krow,      kv[0], kv[1]);
            ld4(krow + 32, kv[2], kv[3]);
        }

        u64 a0 = f2_mul(q0[0], kv[0]);
        a0 = f2_fma(q0[1], kv[1], a0);
        a0 = f2_fma(q0[2], kv[2], a0);
        a0 = f2_fma(q0[3], kv[3], a0);
        u64 a1 = f2_mul(q1[0], kv[0]);
        a1 = f2_fma(q1[1], kv[1], a1);
        a1 = f2_fma(q1[2], kv[2], a1);
        a1 = f2_fma(q1[3], kv[3], a1);

        float2 s0 = f2_unpack(a0);
        float2 s1 = f2_unpack(a1);
        float p0 = s0.x + s0.y;
        float p1 = s1.x + s1.y;

        p0 += __shfl_xor_sync(0xffffffffu, p0, 1);
        p0 += __shfl_xor_sync(0xffffffffu, p0, 2);
        p0 += __shfl_xor_sync(0xffffffffu, p0, 4);
        p1 += __shfl_xor_sync(0xffffffffu, p1, 1);
        p1 += __shfl_xor_sync(0xffffffffu, p1, 2);
        p1 += __shfl_xor_sync(0xffffffffu, p1, 4);

        const bool in_seq = (j >= 0) && (j < S_LEN);
        const float e0 = (in_seq && r <= 8) ? __expf(p0) : 0.f;
        const float e1 = (in_seq && r >= 1) ? __expf(p1) : 0.f;
        den0 += e0;
        den1 += e1;

        const int jc = min(max(j, 0), S_LEN - 1);
        u64 vv[4];
        {
            const float* vrow = vb + (size_t)jc * D_MODEL + c0;  // LDG.128 x2
            ld4(vrow,      vv[0], vv[1]);
            ld4(vrow + 32, vv[2], vv[3]);
        }
        const u64 e0p = f2_pack(e0, e0);
        const u64 e1p = f2_pack(e1, e1);
        #pragma unroll
        for (int kk = 0; kk < 4; ++kk) {
            acc0[kk] = f2_fma(e0p, vv[kk], acc0[kk]);
            acc1[kk] = f2_fma(e1p, vv[kk], acc1[kk]);
        }
    }

    const float inv0 = 1.0f / den0;
    const float inv1 = 1.0f / den1;
    const u64 i0p = f2_pack(inv0, inv0);
    const u64 i1p = f2_pack(inv1, inv1);
    float* o0 = ob + (size_t)i0 * D_MODEL + c0;
    float* o1 = ob + (size_t)i1 * D_MODEL + c0;
    st4(o0,      f2_mul(acc0[0], i0p), f2_mul(acc0[1], i0p));
    st4(o0 + 32, f2_mul(acc0[2], i0p), f2_mul(acc0[3], i0p));
    st4(o1,      f2_mul(acc1[0], i1p), f2_mul(acc1[1], i1p));
    st4(o1 + 32, f2_mul(acc1[2], i1p), f2_mul(acc1[3], i1p));
}

extern "C" void kernel_launch(void* const* d_in, const int* in_sizes, int n_in,
                              void* d_out, int out_size)
{
    const float* q = (const float*)d_in[0];
    const float* k = (const float*)d_in[1];
    const float* v = (const float*)d_in[2];
    float* out = (float*)d_out;

    const int smem_bytes = KROWS * 64 * (int)sizeof(float);  // 10240
    cudaFuncSetAttribute(band_attn_kernel,
                         cudaFuncAttributeMaxDynamicSharedMemorySize, smem_bytes);

    const int n_cta = 256 * 16 * 4;  // B * H * 4 quarters
    band_attn_kernel<<<n_cta, THREADS, smem_bytes>>>(q, k, v, out);
}

// round 16
// speedup vs baseline: 1.3184x; 1.0847x over previous
#include <cuda_runtime.h>

// Banded attention |i-j|<=4: B=256, S=128, D=1024, H=16, HD=64, fp32.
// R9 (best: 108.5us) + micro-deltas only:
//  - V-row LDG hoisted ABOVE the shuffle/exp chain (overlaps its latency)
//  - K stage via cp.async.cg (L2-only; keeps L1D for V lines)
//  - branch-free band mask (0/1 multipliers instead of predicated exp)
// Grid 8192: one CTA (128 thr) per (b,h,half) -> 64 queries. K window
// (72 clamped rows) in smem; V from global. 8-lane subgroups, adjacent
// query pairs over shared 10-row window, .128 accesses, 3-step shuffle,
// online softmax, packed f32x2 FMA, 8 CTAs/SM.

constexpr int S_LEN   = 128;
constexpr int D_MODEL = 1024;
constexpr int THREADS = 128;
constexpr int QB      = 64;        // queries per CTA
constexpr int KROWS   = QB + 8;    // 72 staged rows (clamped)
constexpr int WROWS   = 10;

using u64 = unsigned long long;

__device__ __forceinline__ u64 f2_fma(u64 a, u64 b, u64 c) {
    u64 d; asm("fma.rn.f32x2 %0,%1,%2,%3;" : "=l"(d) : "l"(a), "l"(b), "l"(c)); return d;
}
__device__ __forceinline__ u64 f2_mul(u64 a, u64 b) {
    u64 d; asm("mul.rn.f32x2 %0,%1,%2;" : "=l"(d) : "l"(a), "l"(b)); return d;
}
__device__ __forceinline__ u64 f2_pack(float lo, float hi) {
    u64 d; asm("mov.b64 %0,{%1,%2};" : "=l"(d) : "f"(lo), "f"(hi)); return d;
}
__device__ __forceinline__ float2 f2_unpack(u64 a) {
    float lo, hi; asm("mov.b64 {%0,%1},%2;" : "=f"(lo), "=f"(hi) : "l"(a));
    return make_float2(lo, hi);
}
__device__ __forceinline__ void ld4(const float* __restrict__ p, u64& a, u64& b) {
    float4 f = *reinterpret_cast<const float4*>(p);
    a = f2_pack(f.x, f.y);
    b = f2_pack(f.z, f.w);
}
__device__ __forceinline__ void st4(float* __restrict__ p, u64 a, u64 b) {
    float2 lo = f2_unpack(a), hi = f2_unpack(b);
    *reinterpret_cast<float4*>(p) = make_float4(lo.x, lo.y, hi.x, hi.y);
}
__device__ __forceinline__ void cp_async16_cg(unsigned s, const void* g) {
    asm volatile("cp.async.cg.shared.global [%0], [%1], 16;" :: "r"(s), "l"(g));
}

__global__ __launch_bounds__(THREADS, 8)
void band_attn_kernel(const float* __restrict__ q,
                      const float* __restrict__ k,
                      const float* __restrict__ v,
                      float* __restrict__ out)
{
    extern __shared__ float smem[];   // K window [72][64]
    float* ks = smem;

    const int tid   = threadIdx.x;
    const int cta   = blockIdx.x;     // 0..8191
    const int bh    = cta >> 1;
    const int half  = cta & 1;
    const int qbase = half * QB;
    const int b     = bh >> 4;
    const int h     = bh & 15;
    const size_t base = (size_t)b * S_LEN * D_MODEL + (size_t)h * 64;

    const float* kb = k   + base;
    const float* vb = v   + base;
    const float* qb = q   + base;
    float*       ob = out + base;

    // Stage K window (L2-only): smem row r holds K[clamp(qbase-4+r)].
    const unsigned ks_s = (unsigned)__cvta_generic_to_shared(ks);
    #pragma unroll
    for (int it = 0; it < 9; ++it) {
        int idx = it * THREADS + tid;       // 0..1151
        int row = idx >> 4;
        int c4  = idx & 15;
        int gr  = min(max(qbase - 4 + row, 0), S_LEN - 1);
        cp_async16_cg(ks_s + (unsigned)(row * 64 + c4 * 4) * 4u,
                      kb + (size_t)gr * D_MODEL + c4 * 4);
    }
    asm volatile("cp.async.commit_group;");

    const int warp = tid >> 5;              // 0..3
    const int lane = tid & 31;
    const int g    = lane >> 3;             // subgroup 0..3
    const int l    = lane & 7;
    const int c0   = 4 * l;
    const u64 scale2 = f2_pack(0.125f, 0.125f);

    // Hoist t=0 Q loads: they fly while the K stage is in-flight.
    u64 q0[4], q1[4];
    {
        const int i0 = qbase + warp * 16 + g * 2;
        const float* q0p = qb + (size_t)i0 * D_MODEL + c0;
        const float* q1p = qb + (size_t)(i0 + 1) * D_MODEL + c0;
        ld4(q0p,      q0[0], q0[1]);
        ld4(q0p + 32, q0[2], q0[3]);
        ld4(q1p,      q1[0], q1[1]);
        ld4(q1p + 32, q1[2], q1[3]);
        #pragma unroll
        for (int kk = 0; kk < 4; ++kk) {
            q0[kk] = f2_mul(q0[kk], scale2);
            q1[kk] = f2_mul(q1[kk], scale2);
        }
    }

    asm volatile("cp.async.wait_group 0;");
    __syncthreads();

    #pragma unroll 1
    for (int t = 0; t < 2; ++t) {
        const int il = warp * 16 + t * 8 + g * 2;   // CTA-local even query
        const int i0 = qbase + il;
        const int i1 = i0 + 1;

        if (t == 1) {
            const float* q0p = qb + (size_t)i0 * D_MODEL + c0;
            const float* q1p = qb + (size_t)i1 * D_MODEL + c0;
            ld4(q0p,      q0[0], q0[1]);
            ld4(q0p + 32, q0[2], q0[3]);
            ld4(q1p,      q1[0], q1[1]);
            ld4(q1p + 32, q1[2], q1[3]);
            #pragma unroll
            for (int kk = 0; kk < 4; ++kk) {
                q0[kk] = f2_mul(q0[kk], scale2);
                q1[kk] = f2_mul(q1[kk], scale2);
            }
        }

        float den0 = 0.f, den1 = 0.f;
        u64 acc0[4] = {0, 0, 0, 0};
        u64 acc1[4] = {0, 0, 0, 0};

        #pragma unroll
        for (int r = 0; r < WROWS; ++r) {
            const int j = i0 - 4 + r;
            const int jc = min(max(j, 0), S_LEN - 1);
            const bool in_seq = (j >= 0) && (j < S_LEN);
            const float m0 = (in_seq && r <= 8) ? 1.f : 0.f;
            const float m1 = (in_seq && r >= 1) ? 1.f : 0.f;

            // K row from smem.
            u64 kv[4];
            {
                const float* krow = ks + (il + r) * 64 + c0;   // LDS.128 x2
                ld4(krow,      kv[0], kv[1]);
                ld4(krow + 32, kv[2], kv[3]);
            }

            // V row LDG issued EARLY: latency hidden under shuffles+exp below.
            u64 vv[4];
            {
                const float* vrow = vb + (size_t)jc * D_MODEL + c0;  // LDG.128 x2
                ld4(vrow,      vv[0], vv[1]);
                ld4(vrow + 32, vv[2], vv[3]);
            }

            u64 a0 = f2_mul(q0[0], kv[0]);
            a0 = f2_fma(q0[1], kv[1], a0);
            a0 = f2_fma(q0[2], kv[2], a0);
            a0 = f2_fma(q0[3], kv[3], a0);
            u64 a1 = f2_mul(q1[0], kv[0]);
            a1 = f2_fma(q1[1], kv[1], a1);
            a1 = f2_fma(q1[2], kv[2], a1);
            a1 = f2_fma(q1[3], kv[3], a1);

            float2 s0 = f2_unpack(a0);
            float2 s1 = f2_unpack(a1);
            float p0 = s0.x + s0.y;
            float p1 = s1.x + s1.y;

            p0 += __shfl_xor_sync(0xffffffffu, p0, 1);
            p1 += __shfl_xor_sync(0xffffffffu, p1, 1);
            p0 += __shfl_xor_sync(0xffffffffu, p0, 2);
            p1 += __shfl_xor_sync(0xffffffffu, p1, 2);
            p0 += __shfl_xor_sync(0xffffffffu, p0, 4);
            p1 += __shfl_xor_sync(0xffffffffu, p1, 4);

            // Branch-free mask: exp always computed, zeroed by multiplier.
            const float e0 = m0 * __expf(p0);
            const float e1 = m1 * __expf(p1);
            den0 += e0;
            den1 += e1;

            const u64 e0p = f2_pack(e0, e0);
            const u64 e1p = f2_pack(e1, e1);
            #pragma unroll
            for (int kk = 0; kk < 4; ++kk) {
                acc0[kk] = f2_fma(e0p, vv[kk], acc0[kk]);
                acc1[kk] = f2_fma(e1p, vv[kk], acc1[kk]);
            }
        }

        const float inv0 = 1.0f / den0;
        const float inv1 = 1.0f / den1;
        const u64 i0p = f2_pack(inv0, inv0);
        const u64 i1p = f2_pack(inv1, inv1);
        float* o0 = ob + (size_t)i0 * D_MODEL + c0;
        float* o1 = ob + (size_t)i1 * D_MODEL + c0;
        st4(o0,      f2_mul(acc0[0], i0p), f2_mul(acc0[1], i0p));
        st4(o0 + 32, f2_mul(acc0[2], i0p), f2_mul(acc0[3], i0p));
        st4(o1,      f2_mul(acc1[0], i1p), f2_mul(acc1[1], i1p));
        st4(o1 + 32, f2_mul(acc1[2], i1p), f2_mul(acc1[3], i1p));
    }
}

extern "C" void kernel_launch(void* const* d_in, const int* in_sizes, int n_in,
                              void* d_out, int out_size)
{
    const float* q = (const float*)d_in[0];
    const float* k = (const float*)d_in[1];
    const float* v = (const float*)d_in[2];
    float* out = (float*)d_out;

    const int smem_bytes = KROWS * 64 * (int)sizeof(float);  // 18432
    cudaFuncSetAttribute(band_attn_kernel,
                         cudaFuncAttributeMaxDynamicSharedMemorySize, smem_bytes);

    const int n_cta = 256 * 16 * 2;  // B * H * 2 halves
    band_attn_kernel<<<n_cta, THREADS, smem_bytes>>>(q, k, v, out);
}

// round 17
// speedup vs baseline: 1.3753x; 1.0431x over previous
#include <cuda_runtime.h>

// Banded attention |i-j|<=4: B=256, S=128, D=1024, H=16, HD=64, fp32.
// R9 (best: 108.5us) byte-for-byte, ONE delta: 1.0f/den -> __fdividef
// (MUFU.RCP path trims ~15 instrs off each t-iteration's serial tail).
// Grid 8192: one CTA (128 thr) per (b,h,half) -> 64 queries. K window (72
// clamped rows, 18.4KB) staged via cp.async.ca; V from global (L1/L2).
// 8-lane subgroups, adjacent query pairs over a shared 10-row window,
// .128 accesses, 3-step shuffle reduction, online softmax, f32x2 FMA,
// 8 CTAs/SM staggered stage/compute phases.

constexpr int S_LEN   = 128;
constexpr int D_MODEL = 1024;
constexpr int THREADS = 128;
constexpr int QB      = 64;        // queries per CTA
constexpr int KROWS   = QB + 8;    // 72 staged rows (clamped)
constexpr int WROWS   = 10;

using u64 = unsigned long long;

__device__ __forceinline__ u64 f2_fma(u64 a, u64 b, u64 c) {
    u64 d; asm("fma.rn.f32x2 %0,%1,%2,%3;" : "=l"(d) : "l"(a), "l"(b), "l"(c)); return d;
}
__device__ __forceinline__ u64 f2_mul(u64 a, u64 b) {
    u64 d; asm("mul.rn.f32x2 %0,%1,%2;" : "=l"(d) : "l"(a), "l"(b)); return d;
}
__device__ __forceinline__ u64 f2_pack(float lo, float hi) {
    u64 d; asm("mov.b64 %0,{%1,%2};" : "=l"(d) : "f"(lo), "f"(hi)); return d;
}
__device__ __forceinline__ float2 f2_unpack(u64 a) {
    float lo, hi; asm("mov.b64 {%0,%1},%2;" : "=f"(lo), "=f"(hi) : "l"(a));
    return make_float2(lo, hi);
}
__device__ __forceinline__ void ld4(const float* __restrict__ p, u64& a, u64& b) {
    float4 f = *reinterpret_cast<const float4*>(p);
    a = f2_pack(f.x, f.y);
    b = f2_pack(f.z, f.w);
}
__device__ __forceinline__ void st4(float* __restrict__ p, u64 a, u64 b) {
    float2 lo = f2_unpack(a), hi = f2_unpack(b);
    *reinterpret_cast<float4*>(p) = make_float4(lo.x, lo.y, hi.x, hi.y);
}
__device__ __forceinline__ void cp_async16(unsigned s, const void* g) {
    asm volatile("cp.async.ca.shared.global [%0], [%1], 16;" :: "r"(s), "l"(g));
}

__global__ __launch_bounds__(THREADS, 8)
void band_attn_kernel(const float* __restrict__ q,
                      const float* __restrict__ k,
                      const float* __restrict__ v,
                      float* __restrict__ out)
{
    extern __shared__ float smem[];   // K window [72][64]
    float* ks = smem;

    const int tid   = threadIdx.x;
    const int cta   = blockIdx.x;     // 0..8191
    const int bh    = cta >> 1;
    const int half  = cta & 1;
    const int qbase = half * QB;
    const int b     = bh >> 4;
    const int h     = bh & 15;
    const size_t base = (size_t)b * S_LEN * D_MODEL + (size_t)h * 64;

    const float* kb = k   + base;
    const float* vb = v   + base;
    const float* qb = q   + base;
    float*       ob = out + base;

    // Stage K window: smem row r holds K[clamp(qbase-4+r)]. 1152 x 16B chunks.
    const unsigned ks_s = (unsigned)__cvta_generic_to_shared(ks);
    #pragma unroll
    for (int it = 0; it < 9; ++it) {
        int idx = it * THREADS + tid;       // 0..1151
        int row = idx >> 4;
        int c4  = idx & 15;
        int gr  = min(max(qbase - 4 + row, 0), S_LEN - 1);
        cp_async16(ks_s + (unsigned)(row * 64 + c4 * 4) * 4u,
                   kb + (size_t)gr * D_MODEL + c4 * 4);
    }
    asm volatile("cp.async.commit_group;");

    const int warp = tid >> 5;              // 0..3
    const int lane = tid & 31;
    const int g    = lane >> 3;             // subgroup 0..3
    const int l    = lane & 7;
    const int c0   = 4 * l;
    const u64 scale2 = f2_pack(0.125f, 0.125f);

    // Hoist t=0 Q loads: these LDGs fly while the K stage is in-flight.
    u64 q0[4], q1[4];
    {
        const int i0 = qbase + warp * 16 + g * 2;
        const float* q0p = qb + (size_t)i0 * D_MODEL + c0;
        const float* q1p = qb + (size_t)(i0 + 1) * D_MODEL + c0;
        ld4(q0p,      q0[0], q0[1]);
        ld4(q0p + 32, q0[2], q0[3]);
        ld4(q1p,      q1[0], q1[1]);
        ld4(q1p + 32, q1[2], q1[3]);
        #pragma unroll
        for (int kk = 0; kk < 4; ++kk) {
            q0[kk] = f2_mul(q0[kk], scale2);
            q1[kk] = f2_mul(q1[kk], scale2);
        }
    }

    asm volatile("cp.async.wait_group 0;");
    __syncthreads();

    #pragma unroll 1
    for (int t = 0; t < 2; ++t) {
        const int il = warp * 16 + t * 8 + g * 2;   // CTA-local even query
        const int i0 = qbase + il;
        const int i1 = i0 + 1;

        if (t == 1) {
            const float* q0p = qb + (size_t)i0 * D_MODEL + c0;
            const float* q1p = qb + (size_t)i1 * D_MODEL + c0;
            ld4(q0p,      q0[0], q0[1]);
            ld4(q0p + 32, q0[2], q0[3]);
            ld4(q1p,      q1[0], q1[1]);
            ld4(q1p + 32, q1[2], q1[3]);
            #pragma unroll
            for (int kk = 0; kk < 4; ++kk) {
                q0[kk] = f2_mul(q0[kk], scale2);
                q1[kk] = f2_mul(q1[kk], scale2);
            }
        }

        float den0 = 0.f, den1 = 0.f;
        u64 acc0[4] = {0, 0, 0, 0};
        u64 acc1[4] = {0, 0, 0, 0};

        #pragma unroll
        for (int r = 0; r < WROWS; ++r) {
            const int j = i0 - 4 + r;

            u64 kv[4];
            {
                const float* krow = ks + (il + r) * 64 + c0;   // LDS.128 x2
                ld4(krow,      kv[0], kv[1]);
                ld4(krow + 32, kv[2], kv[3]);
            }

            u64 a0 = f2_mul(q0[0], kv[0]);
            a0 = f2_fma(q0[1], kv[1], a0);
            a0 = f2_fma(q0[2], kv[2], a0);
            a0 = f2_fma(q0[3], kv[3], a0);
            u64 a1 = f2_mul(q1[0], kv[0]);
            a1 = f2_fma(q1[1], kv[1], a1);
            a1 = f2_fma(q1[2], kv[2], a1);
            a1 = f2_fma(q1[3], kv[3], a1);

            float2 s0 = f2_unpack(a0);
            float2 s1 = f2_unpack(a1);
            float p0 = s0.x + s0.y;
            float p1 = s1.x + s1.y;

            p0 += __shfl_xor_sync(0xffffffffu, p0, 1);
            p0 += __shfl_xor_sync(0xffffffffu, p0, 2);
            p0 += __shfl_xor_sync(0xffffffffu, p0, 4);
            p1 += __shfl_xor_sync(0xffffffffu, p1, 1);
            p1 += __shfl_xor_sync(0xffffffffu, p1, 2);
            p1 += __shfl_xor_sync(0xffffffffu, p1, 4);

            const bool in_seq = (j >= 0) && (j < S_LEN);
            const float e0 = (in_seq && r <= 8) ? __expf(p0) : 0.f;
            const float e1 = (in_seq && r >= 1) ? __expf(p1) : 0.f;
            den0 += e0;
            den1 += e1;

            const int jc = min(max(j, 0), S_LEN - 1);
            u64 vv[4];
            {
                const float* vrow = vb + (size_t)jc * D_MODEL + c0;  // LDG.128 x2
                ld4(vrow,      vv[0], vv[1]);
                ld4(vrow + 32, vv[2], vv[3]);
            }
            const u64 e0p = f2_pack(e0, e0);
            const u64 e1p = f2_pack(e1, e1);
            #pragma unroll
            for (int kk = 0; kk < 4; ++kk) {
                acc0[kk] = f2_fma(e0p, vv[kk], acc0[kk]);
                acc1[kk] = f2_fma(e1p, vv[kk], acc1[kk]);
            }
        }

        // Fast reciprocal: MUFU.RCP path (den in safe range; tol 1e-3).
        const float inv0 = __fdividef(1.0f, den0);
        const float inv1 = __fdividef(1.0f, den1);
        const u64 i0p = f2_pack(inv0, inv0);
        const u64 i1p = f2_pack(inv1, inv1);
        float* o0 = ob + (size_t)i0 * D_MODEL + c0;
        float* o1 = ob + (size_t)i1 * D_MODEL + c0;
        st4(o0,      f2_mul(acc0[0], i0p), f2_mul(acc0[1], i0p));
        st4(o0 + 32, f2_mul(acc0[2], i0p), f2_mul(acc0[3], i0p));
        st4(o1,      f2_mul(acc1[0], i1p), f2_mul(acc1[1], i1p));
        st4(o1 + 32, f2_mul(acc1[2], i1p), f2_mul(acc1[3], i1p));
    }
}

extern "C" void kernel_launch(void* const* d_in, const int* in_sizes, int n_in,
                              void* d_out, int out_size)
{
    const float* q = (const float*)d_in[0];
    const float* k = (const float*)d_in[1];
    const float* v = (const float*)d_in[2];
    float* out = (float*)d_out;

    const int smem_bytes = KROWS * 64 * (int)sizeof(float);  // 18432
    cudaFuncSetAttribute(band_attn_kernel,
                         cudaFuncAttributeMaxDynamicSharedMemorySize, smem_bytes);

    const int n_cta = 256 * 16 * 2;  // B * H * 2 halves
    band_attn_kernel<<<n_cta, THREADS, smem_bytes>>>(q, k, v, out);
}